// round 4
// baseline (speedup 1.0000x reference)
#include <cuda_runtime.h>
#include <cuda_bf16.h>
#include <stdint.h>

// Scratch (no cudaMalloc allowed).
#define MAX_NODES 131072
__device__ unsigned char g_cls[MAX_NODES];  // per-node class (0..C-1)
__device__ double g_sum;
__device__ unsigned int g_count;

// ---------------------------------------------------------------------------
// Kernel 1: pack int32 classes -> uint8 table; reset accumulator + counter.
// Each thread packs 8 nodes (2x int4 load -> one 8B store).
// ---------------------------------------------------------------------------
__global__ void pack_kernel(const int* __restrict__ node_classes, int n_nodes) {
    int q = blockIdx.x * blockDim.x + threadIdx.x;
    if (q == 0) { g_sum = 0.0; g_count = 0u; }

    int base = q * 8;
    if (base + 7 < n_nodes) {
        int4 a = *(const int4*)(node_classes + base);
        int4 b = *(const int4*)(node_classes + base + 4);
        unsigned long long w =
            (unsigned long long)(unsigned char)a.x |
            ((unsigned long long)(unsigned char)a.y << 8) |
            ((unsigned long long)(unsigned char)a.z << 16) |
            ((unsigned long long)(unsigned char)a.w << 24) |
            ((unsigned long long)(unsigned char)b.x << 32) |
            ((unsigned long long)(unsigned char)b.y << 40) |
            ((unsigned long long)(unsigned char)b.z << 48) |
            ((unsigned long long)(unsigned char)b.w << 56);
        *(unsigned long long*)(g_cls + base) = w;
    } else if (base < n_nodes) {
        for (int i = base; i < n_nodes; i++)
            g_cls[i] = (unsigned char)node_classes[i];
    }
}

// ---------------------------------------------------------------------------
// Kernel 2: main edge loop + fused finalize.
//   dyn smem: [0, n_nodes) uint8 class table, then (128B aligned)
//             C*32 uint bank-replicated adjacency masks.
// ---------------------------------------------------------------------------
__global__ void __launch_bounds__(768, 2)
edge_loss_kernel(const float* __restrict__ edge_scores,
                 const int* __restrict__ edge_indices,
                 const float* __restrict__ adj,
                 float* __restrict__ out,
                 int n_edges, int n_nodes, int C) {
    extern __shared__ unsigned char smem[];
    unsigned char* s_tbl = smem;
    int mask_off = (n_nodes + 127) & ~127;
    unsigned int* s_mask = (unsigned int*)(smem + mask_off);

    int tid = threadIdx.x;
    int nthreads = blockDim.x;
    int lane = tid & 31;

    // Stage class table into shared (16B vector copies + byte tail).
    int n16 = n_nodes >> 4;
    const uint4* src16 = (const uint4*)g_cls;
    uint4* dst16 = (uint4*)s_tbl;
    for (int i = tid; i < n16; i += nthreads) dst16[i] = src16[i];
    for (int i = (n16 << 4) + tid; i < n_nodes; i += nthreads) s_tbl[i] = g_cls[i];

    // Bank-replicated adjacency masks: s_mask[cls*32 + lane] == mask[cls].
    // Lane l always reads bank l -> conflict-free gather.
    if (tid < C * 32) {
        int cls = tid >> 5;
        unsigned int m = 0;
        for (int j = 0; j < C; j++)
            m |= (adj[cls * C + j] != 0.0f ? 1u : 0u) << j;
        s_mask[tid] = m;
    }
    __syncthreads();

    const int* src_idx = edge_indices;            // row 0
    const int* dst_idx = edge_indices + n_edges;  // row 1

    int nq = n_edges >> 2;  // groups of 4 edges
    int gtid = blockIdx.x * nthreads + tid;
    int gstride = gridDim.x * nthreads;
    int guard = n_nodes - 1;
    const float LN2 = 0.6931471805599453f;

    float acc = 0.0f;

    #pragma unroll 2
    for (int q = gtid; q < nq; q += gstride) {
        int4 s4 = *(const int4*)(src_idx + 4 * q);
        int4 d4 = *(const int4*)(dst_idx + 4 * q);
        float4 sc = *(const float4*)(edge_scores + 4 * q);

        unsigned a0 = s_tbl[min(s4.x, guard)];
        unsigned b0 = s_tbl[min(d4.x, guard)];
        unsigned a1 = s_tbl[min(s4.y, guard)];
        unsigned b1 = s_tbl[min(d4.y, guard)];
        unsigned a2 = s_tbl[min(s4.z, guard)];
        unsigned b2 = s_tbl[min(d4.z, guard)];
        unsigned a3 = s_tbl[min(s4.w, guard)];
        unsigned b3 = s_tbl[min(d4.w, guard)];

        unsigned y0 = (s_mask[(a0 << 5) | lane] >> b0) & 1u;
        unsigned y1 = (s_mask[(a1 << 5) | lane] >> b1) & 1u;
        unsigned y2 = (s_mask[(a2 << 5) | lane] >> b2) & 1u;
        unsigned y3 = (s_mask[(a3 << 5) | lane] >> b3) & 1u;

        float s0 = sc.x, s1 = sc.y, s2 = sc.z, s3 = sc.w;
        // per_edge = max(s,0) - s*y + log(1 + exp(-|s|))
        float e0 = __expf(-fabsf(s0));
        float e1 = __expf(-fabsf(s1));
        float e2 = __expf(-fabsf(s2));
        float e3 = __expf(-fabsf(s3));
        acc += fmaxf(s0, 0.0f) - (y0 ? s0 : 0.0f) + LN2 * __log2f(1.0f + e0);
        acc += fmaxf(s1, 0.0f) - (y1 ? s1 : 0.0f) + LN2 * __log2f(1.0f + e1);
        acc += fmaxf(s2, 0.0f) - (y2 ? s2 : 0.0f) + LN2 * __log2f(1.0f + e2);
        acc += fmaxf(s3, 0.0f) - (y3 ? s3 : 0.0f) + LN2 * __log2f(1.0f + e3);
    }

    // Tail edges (n_edges % 4).
    if (gtid == 0) {
        for (int e = nq << 2; e < n_edges; e++) {
            unsigned a = s_tbl[min(src_idx[e], guard)];
            unsigned b = s_tbl[min(dst_idx[e], guard)];
            unsigned y = (s_mask[(a << 5) | lane] >> b) & 1u;
            float s = edge_scores[e];
            acc += fmaxf(s, 0.0f) - (y ? s : 0.0f) +
                   LN2 * __log2f(1.0f + __expf(-fabsf(s)));
        }
    }

    // Block reduction: warp shuffle -> shared -> one double atomic per block.
    __shared__ float red[32];
    int wid = tid >> 5;
    #pragma unroll
    for (int off = 16; off > 0; off >>= 1)
        acc += __shfl_xor_sync(0xFFFFFFFFu, acc, off);
    if (lane == 0) red[wid] = acc;
    __syncthreads();
    if (wid == 0) {
        int nw = nthreads >> 5;
        float v = (lane < nw) ? red[lane] : 0.0f;
        #pragma unroll
        for (int off = 16; off > 0; off >>= 1)
            v += __shfl_xor_sync(0xFFFFFFFFu, v, off);
        if (lane == 0) {
            atomicAdd(&g_sum, (double)v);
            __threadfence();
            unsigned done = atomicAdd(&g_count, 1u);
            if (done == gridDim.x - 1) {
                double total = *((volatile double*)&g_sum);
                out[0] = (float)(total / (double)n_edges);
            }
        }
    }
}

extern "C" void kernel_launch(void* const* d_in, const int* in_sizes, int n_in,
                              void* d_out, int out_size) {
    // Inputs: node_classes(int32), edge_scores(f32), edge_indices(int32, 2xN),
    // valid_adjacency(f32, CxC).
    const int* node_classes = (const int*)d_in[0];
    const float* edge_scores = (const float*)d_in[1];
    const int* edge_indices = (const int*)d_in[2];
    const float* adj = (const float*)d_in[3];

    int n_nodes = in_sizes[0];
    int n_edges = in_sizes[1];
    int C = 1;
    while (C * C < in_sizes[3]) C++;  // 144 -> 12

    int mask_off = (n_nodes + 127) & ~127;
    size_t smem_bytes = (size_t)mask_off + (size_t)C * 32 * sizeof(unsigned int);

    cudaFuncSetAttribute(edge_loss_kernel,
                         cudaFuncAttributeMaxDynamicSharedMemorySize,
                         (int)smem_bytes);

    int nsm = 148;
    cudaDeviceGetAttribute(&nsm, cudaDevAttrMultiProcessorCount, 0);

    int pack_threads = 256;
    int pack_blocks = ((n_nodes + 7) / 8 + pack_threads - 1) / pack_threads;
    pack_kernel<<<pack_blocks, pack_threads>>>(node_classes, n_nodes);

    // 2 CTAs per SM (smem ~99.3KB each), 768 threads -> 48 warps/SM.
    edge_loss_kernel<<<2 * nsm, 768, smem_bytes>>>(edge_scores, edge_indices,
                                                   adj, (float*)d_out,
                                                   n_edges, n_nodes, C);
}

// round 7
// speedup vs baseline: 1.0028x; 1.0028x over previous
#include <cuda_runtime.h>
#include <cuda_bf16.h>
#include <stdint.h>

// Scratch (no cudaMalloc allowed).
#define MAX_NODES 131072
__device__ unsigned char g_cls[MAX_NODES];  // per-node class (0..C-1)
__device__ double g_sum;
__device__ unsigned int g_count;

// Prefetch distance in grid-stride iterations (threads run ~8.5 iters total).
#define PF_DIST 4

// ---------------------------------------------------------------------------
// Kernel 1: pack int32 classes -> uint8 table; reset accumulator + counter.
// ---------------------------------------------------------------------------
__global__ void pack_kernel(const int* __restrict__ node_classes, int n_nodes) {
    int q = blockIdx.x * blockDim.x + threadIdx.x;
    if (q == 0) { g_sum = 0.0; g_count = 0u; }

    int base = q * 8;
    if (base + 7 < n_nodes) {
        int4 a = *(const int4*)(node_classes + base);
        int4 b = *(const int4*)(node_classes + base + 4);
        unsigned long long w =
            (unsigned long long)(unsigned char)a.x |
            ((unsigned long long)(unsigned char)a.y << 8) |
            ((unsigned long long)(unsigned char)a.z << 16) |
            ((unsigned long long)(unsigned char)a.w << 24) |
            ((unsigned long long)(unsigned char)b.x << 32) |
            ((unsigned long long)(unsigned char)b.y << 40) |
            ((unsigned long long)(unsigned char)b.z << 48) |
            ((unsigned long long)(unsigned char)b.w << 56);
        *(unsigned long long*)(g_cls + base) = w;
    } else if (base < n_nodes) {
        for (int i = base; i < n_nodes; i++)
            g_cls[i] = (unsigned char)node_classes[i];
    }
}

// ---------------------------------------------------------------------------
// Kernel 2: main edge loop + fused finalize.
//   dyn smem: [0, n_nodes) uint8 class table, then (128B aligned)
//             C*32 uint bank-replicated adjacency masks.
// ---------------------------------------------------------------------------
__global__ void __launch_bounds__(768, 2)
edge_loss_kernel(const float* __restrict__ edge_scores,
                 const int* __restrict__ edge_indices,
                 const float* __restrict__ adj,
                 float* __restrict__ out,
                 int n_edges, int n_nodes, int C) {
    extern __shared__ unsigned char smem[];
    unsigned char* s_tbl = smem;
    int mask_off = (n_nodes + 127) & ~127;
    unsigned int* s_mask = (unsigned int*)(smem + mask_off);

    int tid = threadIdx.x;
    int nthreads = blockDim.x;
    int lane = tid & 31;

    // Stage class table into shared.
    int n16 = n_nodes >> 4;
    const uint4* src16 = (const uint4*)g_cls;
    uint4* dst16 = (uint4*)s_tbl;
    for (int i = tid; i < n16; i += nthreads) dst16[i] = src16[i];
    for (int i = (n16 << 4) + tid; i < n_nodes; i += nthreads) s_tbl[i] = g_cls[i];

    // Bank-replicated adjacency masks: s_mask[cls*32 + lane] == mask[cls].
    if (tid < C * 32) {
        int cls = tid >> 5;
        unsigned int m = 0;
        for (int j = 0; j < C; j++)
            m |= (adj[cls * C + j] != 0.0f ? 1u : 0u) << j;
        s_mask[tid] = m;
    }
    __syncthreads();

    const int* src_idx = edge_indices;            // row 0
    const int* dst_idx = edge_indices + n_edges;  // row 1

    int nq = n_edges >> 2;  // groups of 4 edges per thread-iter
    int gtid = blockIdx.x * nthreads + tid;
    int gstride = gridDim.x * nthreads;
    int guard = n_nodes - 1;
    const float LN2 = 0.6931471805599453f;

    float acc = 0.0f;

    #pragma unroll 2
    for (int q = gtid; q < nq; q += gstride) {
        // L2 prefetch: each lane pulls its own 16B slice PF_DIST strides ahead
        // on all three streams (plain prefetch.global.L2 — LSU path, non-blocking).
        {
            long pf = (long)q + (long)PF_DIST * gstride;
            if (pf < (long)nq) {
                const char* p0 = (const char*)(src_idx + 4 * pf);
                const char* p1 = (const char*)(dst_idx + 4 * pf);
                const char* p2 = (const char*)(edge_scores + 4 * pf);
                asm volatile("prefetch.global.L2 [%0];" :: "l"(p0));
                asm volatile("prefetch.global.L2 [%0];" :: "l"(p1));
                asm volatile("prefetch.global.L2 [%0];" :: "l"(p2));
            }
        }

        int4 s4 = *(const int4*)(src_idx + 4 * q);
        int4 d4 = *(const int4*)(dst_idx + 4 * q);
        float4 sc = *(const float4*)(edge_scores + 4 * q);

        unsigned a0 = s_tbl[min(s4.x, guard)];
        unsigned b0 = s_tbl[min(d4.x, guard)];
        unsigned a1 = s_tbl[min(s4.y, guard)];
        unsigned b1 = s_tbl[min(d4.y, guard)];
        unsigned a2 = s_tbl[min(s4.z, guard)];
        unsigned b2 = s_tbl[min(d4.z, guard)];
        unsigned a3 = s_tbl[min(s4.w, guard)];
        unsigned b3 = s_tbl[min(d4.w, guard)];

        unsigned y0 = (s_mask[(a0 << 5) | lane] >> b0) & 1u;
        unsigned y1 = (s_mask[(a1 << 5) | lane] >> b1) & 1u;
        unsigned y2 = (s_mask[(a2 << 5) | lane] >> b2) & 1u;
        unsigned y3 = (s_mask[(a3 << 5) | lane] >> b3) & 1u;

        float s0 = sc.x, s1 = sc.y, s2 = sc.z, s3 = sc.w;
        // per_edge = max(s,0) - s*y + log(1 + exp(-|s|))
        float e0 = __expf(-fabsf(s0));
        float e1 = __expf(-fabsf(s1));
        float e2 = __expf(-fabsf(s2));
        float e3 = __expf(-fabsf(s3));
        acc += fmaxf(s0, 0.0f) - (y0 ? s0 : 0.0f) + LN2 * __log2f(1.0f + e0);
        acc += fmaxf(s1, 0.0f) - (y1 ? s1 : 0.0f) + LN2 * __log2f(1.0f + e1);
        acc += fmaxf(s2, 0.0f) - (y2 ? s2 : 0.0f) + LN2 * __log2f(1.0f + e2);
        acc += fmaxf(s3, 0.0f) - (y3 ? s3 : 0.0f) + LN2 * __log2f(1.0f + e3);
    }

    // Tail edges (n_edges % 4).
    if (gtid == 0) {
        for (int e = nq << 2; e < n_edges; e++) {
            unsigned a = s_tbl[min(src_idx[e], guard)];
            unsigned b = s_tbl[min(dst_idx[e], guard)];
            unsigned y = (s_mask[(a << 5) | lane] >> b) & 1u;
            float s = edge_scores[e];
            acc += fmaxf(s, 0.0f) - (y ? s : 0.0f) +
                   LN2 * __log2f(1.0f + __expf(-fabsf(s)));
        }
    }

    // Block reduction: warp shuffle -> shared -> one double atomic per block.
    __shared__ float red[32];
    int wid = tid >> 5;
    #pragma unroll
    for (int off = 16; off > 0; off >>= 1)
        acc += __shfl_xor_sync(0xFFFFFFFFu, acc, off);
    if (lane == 0) red[wid] = acc;
    __syncthreads();
    if (wid == 0) {
        int nw = nthreads >> 5;
        float v = (lane < nw) ? red[lane] : 0.0f;
        #pragma unroll
        for (int off = 16; off > 0; off >>= 1)
            v += __shfl_xor_sync(0xFFFFFFFFu, v, off);
        if (lane == 0) {
            atomicAdd(&g_sum, (double)v);
            __threadfence();
            unsigned done = atomicAdd(&g_count, 1u);
            if (done == gridDim.x - 1) {
                double total = *((volatile double*)&g_sum);
                out[0] = (float)(total / (double)n_edges);
            }
        }
    }
}

extern "C" void kernel_launch(void* const* d_in, const int* in_sizes, int n_in,
                              void* d_out, int out_size) {
    // Inputs: node_classes(int32), edge_scores(f32), edge_indices(int32, 2xN),
    // valid_adjacency(f32, CxC).
    const int* node_classes = (const int*)d_in[0];
    const float* edge_scores = (const float*)d_in[1];
    const int* edge_indices = (const int*)d_in[2];
    const float* adj = (const float*)d_in[3];

    int n_nodes = in_sizes[0];
    int n_edges = in_sizes[1];
    int C = 1;
    while (C * C < in_sizes[3]) C++;  // 144 -> 12

    int mask_off = (n_nodes + 127) & ~127;
    size_t smem_bytes = (size_t)mask_off + (size_t)C * 32 * sizeof(unsigned int);

    cudaFuncSetAttribute(edge_loss_kernel,
                         cudaFuncAttributeMaxDynamicSharedMemorySize,
                         (int)smem_bytes);

    int nsm = 148;
    cudaDeviceGetAttribute(&nsm, cudaDevAttrMultiProcessorCount, 0);

    int pack_threads = 256;
    int pack_blocks = ((n_nodes + 7) / 8 + pack_threads - 1) / pack_threads;
    pack_kernel<<<pack_blocks, pack_threads>>>(node_classes, n_nodes);

    // 2 CTAs per SM (smem ~99.3KB each), 768 threads -> 48 warps/SM.
    edge_loss_kernel<<<2 * nsm, 768, smem_bytes>>>(edge_scores, edge_indices,
                                                   adj, (float*)d_out,
                                                   n_edges, n_nodes, C);
}

// round 9
// speedup vs baseline: 1.0139x; 1.0111x over previous
#include <cuda_runtime.h>
#include <cuda_bf16.h>
#include <stdint.h>

// Scratch (no cudaMalloc allowed).
#define MAX_NODES 131072
__device__ unsigned char g_cls[MAX_NODES];  // per-node class (0..C-1)
__device__ double g_sum;
__device__ unsigned int g_count;

// 32B (256-bit) stream loads with L2 evict_last. sm_103a ptxas requires the
// .v8.b32 form for this hint. Pins the (96MB < 126MB L2) streams in L2 across
// graph replays so steady-state replays run at L2 bandwidth; also halves the
// number of LDGs per byte (fewer L1tex wavefronts / miss entries).
#define LDG_EL_V8(v0, v1, v2, v3, v4, v5, v6, v7, p)                          \
    asm volatile(                                                              \
        "ld.global.nc.L2::evict_last.v8.b32 "                                  \
        "{%0,%1,%2,%3,%4,%5,%6,%7}, [%8];"                                     \
        : "=r"(v0), "=r"(v1), "=r"(v2), "=r"(v3),                              \
          "=r"(v4), "=r"(v5), "=r"(v6), "=r"(v7)                               \
        : "l"(p))

// ---------------------------------------------------------------------------
// Kernel 1: pack int32 classes -> uint8 table; reset accumulator + counter.
// ---------------------------------------------------------------------------
__global__ void pack_kernel(const int* __restrict__ node_classes, int n_nodes) {
    int q = blockIdx.x * blockDim.x + threadIdx.x;
    if (q == 0) { g_sum = 0.0; g_count = 0u; }

    int base = q * 8;
    if (base + 7 < n_nodes) {
        int4 a = *(const int4*)(node_classes + base);
        int4 b = *(const int4*)(node_classes + base + 4);
        unsigned long long w =
            (unsigned long long)(unsigned char)a.x |
            ((unsigned long long)(unsigned char)a.y << 8) |
            ((unsigned long long)(unsigned char)a.z << 16) |
            ((unsigned long long)(unsigned char)a.w << 24) |
            ((unsigned long long)(unsigned char)b.x << 32) |
            ((unsigned long long)(unsigned char)b.y << 40) |
            ((unsigned long long)(unsigned char)b.z << 48) |
            ((unsigned long long)(unsigned char)b.w << 56);
        *(unsigned long long*)(g_cls + base) = w;
    } else if (base < n_nodes) {
        for (int i = base; i < n_nodes; i++)
            g_cls[i] = (unsigned char)node_classes[i];
    }
}

// ---------------------------------------------------------------------------
// Kernel 2: main edge loop + fused finalize. 8 edges per thread-iteration.
//   dyn smem: [0, n_nodes) uint8 class table, then (128B aligned)
//             C*32 uint bank-replicated adjacency masks.
// ---------------------------------------------------------------------------
__global__ void __launch_bounds__(768, 2)
edge_loss_kernel(const float* __restrict__ edge_scores,
                 const int* __restrict__ edge_indices,
                 const float* __restrict__ adj,
                 float* __restrict__ out,
                 int n_edges, int n_nodes, int C) {
    extern __shared__ unsigned char smem[];
    unsigned char* s_tbl = smem;
    int mask_off = (n_nodes + 127) & ~127;
    unsigned int* s_mask = (unsigned int*)(smem + mask_off);

    int tid = threadIdx.x;
    int nthreads = blockDim.x;
    int lane = tid & 31;

    // Stage class table into shared.
    int n16 = n_nodes >> 4;
    const uint4* src16 = (const uint4*)g_cls;
    uint4* dst16 = (uint4*)s_tbl;
    for (int i = tid; i < n16; i += nthreads) dst16[i] = src16[i];
    for (int i = (n16 << 4) + tid; i < n_nodes; i += nthreads) s_tbl[i] = g_cls[i];

    // Bank-replicated adjacency masks: s_mask[cls*32 + lane] == mask[cls].
    if (tid < C * 32) {
        int cls = tid >> 5;
        unsigned int m = 0;
        for (int j = 0; j < C; j++)
            m |= (adj[cls * C + j] != 0.0f ? 1u : 0u) << j;
        s_mask[tid] = m;
    }
    __syncthreads();

    const int* src_idx = edge_indices;            // row 0
    const int* dst_idx = edge_indices + n_edges;  // row 1

    int nq = n_edges >> 3;  // groups of 8 edges per thread-iter
    int gtid = blockIdx.x * nthreads + tid;
    int gstride = gridDim.x * nthreads;
    int guard = n_nodes - 1;
    const float LN2 = 0.6931471805599453f;

    float acc = 0.0f;

    for (int q = gtid; q < nq; q += gstride) {
        int s[8], d[8];
        unsigned sc[8];
        LDG_EL_V8(s[0], s[1], s[2], s[3], s[4], s[5], s[6], s[7],
                  src_idx + 8 * q);
        LDG_EL_V8(d[0], d[1], d[2], d[3], d[4], d[5], d[6], d[7],
                  dst_idx + 8 * q);
        LDG_EL_V8(sc[0], sc[1], sc[2], sc[3], sc[4], sc[5], sc[6], sc[7],
                  edge_scores + 8 * q);

        #pragma unroll
        for (int k = 0; k < 8; k++) {
            unsigned a = s_tbl[min(s[k], guard)];
            unsigned b = s_tbl[min(d[k], guard)];
            unsigned y = (s_mask[(a << 5) | lane] >> b) & 1u;
            float v = __uint_as_float(sc[k]);
            // per_edge = max(v,0) - v*y + log(1 + exp(-|v|))
            float e = __expf(-fabsf(v));
            acc += fmaxf(v, 0.0f) - (y ? v : 0.0f) + LN2 * __log2f(1.0f + e);
        }
    }

    // Tail edges (n_edges % 8).
    if (gtid == 0) {
        for (int e = nq << 3; e < n_edges; e++) {
            unsigned a = s_tbl[min(src_idx[e], guard)];
            unsigned b = s_tbl[min(dst_idx[e], guard)];
            unsigned y = (s_mask[(a << 5) | lane] >> b) & 1u;
            float v = edge_scores[e];
            acc += fmaxf(v, 0.0f) - (y ? v : 0.0f) +
                   LN2 * __log2f(1.0f + __expf(-fabsf(v)));
        }
    }

    // Block reduction: warp shuffle -> shared -> one double atomic per block.
    __shared__ float red[32];
    int wid = tid >> 5;
    #pragma unroll
    for (int off = 16; off > 0; off >>= 1)
        acc += __shfl_xor_sync(0xFFFFFFFFu, acc, off);
    if (lane == 0) red[wid] = acc;
    __syncthreads();
    if (wid == 0) {
        int nw = nthreads >> 5;
        float v = (lane < nw) ? red[lane] : 0.0f;
        #pragma unroll
        for (int off = 16; off > 0; off >>= 1)
            v += __shfl_xor_sync(0xFFFFFFFFu, v, off);
        if (lane == 0) {
            atomicAdd(&g_sum, (double)v);
            __threadfence();
            unsigned done = atomicAdd(&g_count, 1u);
            if (done == gridDim.x - 1) {
                double total = *((volatile double*)&g_sum);
                out[0] = (float)(total / (double)n_edges);
            }
        }
    }
}

extern "C" void kernel_launch(void* const* d_in, const int* in_sizes, int n_in,
                              void* d_out, int out_size) {
    // Inputs: node_classes(int32), edge_scores(f32), edge_indices(int32, 2xN),
    // valid_adjacency(f32, CxC).
    const int* node_classes = (const int*)d_in[0];
    const float* edge_scores = (const float*)d_in[1];
    const int* edge_indices = (const int*)d_in[2];
    const float* adj = (const float*)d_in[3];

    int n_nodes = in_sizes[0];
    int n_edges = in_sizes[1];
    int C = 1;
    while (C * C < in_sizes[3]) C++;  // 144 -> 12

    int mask_off = (n_nodes + 127) & ~127;
    size_t smem_bytes = (size_t)mask_off + (size_t)C * 32 * sizeof(unsigned int);

    cudaFuncSetAttribute(edge_loss_kernel,
                         cudaFuncAttributeMaxDynamicSharedMemorySize,
                         (int)smem_bytes);

    int nsm = 148;
    cudaDeviceGetAttribute(&nsm, cudaDevAttrMultiProcessorCount, 0);

    int pack_threads = 256;
    int pack_blocks = ((n_nodes + 7) / 8 + pack_threads - 1) / pack_threads;
    pack_kernel<<<pack_blocks, pack_threads>>>(node_classes, n_nodes);

    // 2 CTAs per SM (smem ~99.3KB each), 768 threads -> 48 warps/SM.
    edge_loss_kernel<<<2 * nsm, 768, smem_bytes>>>(edge_scores, edge_indices,
                                                   adj, (float*)d_out,
                                                   n_edges, n_nodes, C);
}